// round 14
// baseline (speedup 1.0000x reference)
#include <cuda_runtime.h>

// knnLoss: x-counting-sort + fixed 2048-target window scan (exact w/ coverage
// check + full-scan fallback). Separate graph-captured kernels; the only hot
// kernel is a perfectly balanced 512-block smem FFMA2 scan.

#define NPTS   16384
#define NB     2
#define NQ     (NB * NPTS)
#define NBINS  512
#define XMIN   (-4.5f)
#define BINSCL (NBINS / 9.0f)
#define WBIN   (9.0f / NBINS)
#define WIN    2048
#define HWIN   (WIN / 2)
#define SPLIT  4
#define SEG    (WIN / SPLIT)      // 512 targets per scan block
#define KTHR   128                // scan block threads (QPT=2 -> 256 queries)
#define NCHUNK 128                // sorted 256-query chunks

__device__ int g_thist[NB * NBINS];
__device__ int g_qhist[NB * NBINS];
__device__ int g_tbase[NB * NBINS];
__device__ int g_tcur [NB * NBINS];
__device__ int g_qcur [NB * NBINS];
__device__ __align__(16) float g_sx[NQ];
__device__ __align__(16) float g_sy[NQ];
__device__ __align__(16) float g_sz[NQ];
__device__ __align__(16) float g_sw[NQ];
__device__ float4    g_q[NQ];
__device__ float     g_part[SPLIT * NQ * 3];
__device__ float     g_d[NQ];
__device__ int       g_fb[NQ];
__device__ int       g_fbn;          // zeroed at load; re-zeroed by final_kernel
__device__ long long g_psum[NCHUNK];
__device__ int       g_pcnt[NCHUNK];

#define FMA2(d, a, b, c) \
    asm("fma.rn.f32x2 %0, %1, %2, %3;" : "=l"(d) : "l"(a), "l"(b), "l"(c))
#define UNPK2(lo, hi, v) \
    asm("mov.b64 {%0, %1}, %2;" : "=f"(lo), "=f"(hi) : "l"(v))
#define DUP2(d, f) \
    asm("mov.b64 %0, {%1, %1};" : "=l"(d) : "f"(f))

__device__ __forceinline__ int xbin(float x) {
    int b = (int)((x - XMIN) * BINSCL);
    return min(max(b, 0), NBINS - 1);
}

__device__ __forceinline__ void top3_insert(float r, float& b0, float& b1, float& b2) {
    float m1 = fmaxf(r, b1);
    float m0 = fmaxf(r, b0);
    b2 = fminf(b2, m1);
    b1 = fminf(b1, m0);
    b0 = fminf(b0, r);
}

__device__ __forceinline__ int window_lo(int b, float xc) {
    int pos = g_tbase[b * NBINS + xbin(xc)];
    return (min(max(pos - HWIN, 0), NPTS - WIN)) & ~3;
}

// ---------------- pipeline ----------------

__global__ void hist_kernel(const float* __restrict__ src,
                            const float* __restrict__ tgt) {
    int i = blockIdx.x * blockDim.x + threadIdx.x;    // 0..NQ-1
    int b = i >> 14;
    int n = i & (NPTS - 1);
    int h = n >> 9;
    int w = n & 511;
    long sOff = (((long)b * 64 + 2 * h) * 2048 + 4 * w) * 3;
    long tOff = (long)b * 3 * 64 * 2048 + (long)(2 * h) * 2048 + 4 * w;
    atomicAdd(&g_thist[b * NBINS + xbin(tgt[tOff])], 1);
    atomicAdd(&g_qhist[b * NBINS + xbin(src[sOff])], 1);
}

__global__ __launch_bounds__(256) void prefix_kernel() {
    __shared__ int sh[NBINS];
    int t = threadIdx.x;
    int a = blockIdx.x;                               // 0..3
    const int* h = (a < 2) ? (g_thist + a * NBINS) : (g_qhist + (a - 2) * NBINS);
    int o0 = h[t];
    int o1 = h[t + 256];
    sh[t] = o0;
    sh[t + 256] = o1;
    __syncthreads();
    for (int off = 1; off < NBINS; off <<= 1) {
        int v0 = (t >= off) ? sh[t - off] : 0;
        int v1 = (t + 256 >= off) ? sh[t + 256 - off] : 0;
        __syncthreads();
        sh[t] += v0;
        sh[t + 256] += v1;
        __syncthreads();
    }
    int e0 = sh[t] - o0;
    int e1 = sh[t + 256] - o1;
    if (a < 2) {
        g_tbase[a * NBINS + t] = e0;
        g_tbase[a * NBINS + t + 256] = e1;
        g_tcur [a * NBINS + t] = e0;
        g_tcur [a * NBINS + t + 256] = e1;
    } else {
        g_qcur[(a - 2) * NBINS + t] = e0;
        g_qcur[(a - 2) * NBINS + t + 256] = e1;
    }
}

__global__ void scatter_kernel(const float* __restrict__ src,
                               const float* __restrict__ tgt) {
    int i = blockIdx.x * blockDim.x + threadIdx.x;
    // re-zero hists for the next graph replay (prefix already consumed them)
    if (i < NB * NBINS) g_thist[i] = 0;
    else if (i < 2 * NB * NBINS) g_qhist[i - NB * NBINS] = 0;

    int b = i >> 14;
    int n = i & (NPTS - 1);
    int h = n >> 9;
    int w = n & 511;
    long tOff = (long)b * 3 * 64 * 2048 + (long)(2 * h) * 2048 + 4 * w;
    float tx = tgt[tOff];
    float ty = tgt[tOff + 64 * 2048];
    float tz = tgt[tOff + 2L * 64 * 2048];
    bool  vt = (tx != 0.0f) || (ty != 0.0f) || (tz != 0.0f);
    float tw;
    if (vt) tw = tx * tx + ty * ty + tz * tz;
    else { tx = 0.0f; ty = 0.0f; tz = 0.0f; tw = 1e20f; }
    int tpos = atomicAdd(&g_tcur[b * NBINS + xbin(tx)], 1);
    int ts = b * NPTS + tpos;
    g_sx[ts] = tx; g_sy[ts] = ty; g_sz[ts] = tz; g_sw[ts] = tw;

    long sOff = (((long)b * 64 + 2 * h) * 2048 + 4 * w) * 3;
    float sx = src[sOff + 0];
    float sy = src[sOff + 1];
    float sz = src[sOff + 2];
    bool  vs = (sx != 0.0f) || (sy != 0.0f) || (sz != 0.0f);
    float sq = sx * sx + sy * sy + sz * sz;
    int qpos = atomicAdd(&g_qcur[b * NBINS + xbin(sx)], 1);
    g_q[b * NPTS + qpos] = make_float4(-2.0f * sx, -2.0f * sy, -2.0f * sz,
                                       vs ? sq : -1.0f);
}

// ---------------- hot kernel: balanced window scan ----------------

__global__ __launch_bounds__(KTHR) void scan_kernel() {
    __shared__ ulonglong2 s_x[SEG / 4], s_y[SEG / 4];
    __shared__ ulonglong2 s_z[SEG / 4], s_w[SEG / 4];

    int tid   = threadIdx.x;
    int chunk = blockIdx.x;                 // 0..127
    int sp    = blockIdx.y;                 // 0..3
    int b     = chunk >> 6;
    int qbase = b * NPTS + (chunk & 63) * 256;
    int q0    = qbase + tid;
    int q1    = q0 + KTHR;

    float4 sA = g_q[q0];
    float4 sB = g_q[q1];
    unsigned long long ax, ay, az, bx, by, bz;
    DUP2(ax, sA.x); DUP2(ay, sA.y); DUP2(az, sA.z);
    DUP2(bx, sB.x); DUP2(by, sB.y); DUP2(bz, sB.z);

    float xc = -0.5f * g_q[qbase + 128].x;
    int seg  = window_lo(b, xc) + sp * SEG;

    // cooperative tile load (512 targets, SoA)
    {
        int gbase = b * NPTS + seg;
        const float4* px = (const float4*)(g_sx + gbase);
        const float4* py = (const float4*)(g_sy + gbase);
        const float4* pz = (const float4*)(g_sz + gbase);
        const float4* pw = (const float4*)(g_sw + gbase);
        float4 vx = px[tid]; s_x[tid] = *(const ulonglong2*)&vx;
        float4 vy = py[tid]; s_y[tid] = *(const ulonglong2*)&vy;
        float4 vz = pz[tid]; s_z[tid] = *(const ulonglong2*)&vz;
        float4 vw = pw[tid]; s_w[tid] = *(const ulonglong2*)&vw;
    }
    __syncthreads();

    float a0 = 3e38f, a1 = 3e38f, a2 = 3e38f;
    float c0 = 3e38f, c1 = 3e38f, c2 = 3e38f;

#pragma unroll 4
    for (int j = 0; j < SEG / 4; j++) {
        ulonglong2 xv = s_x[j];
        ulonglong2 yv = s_y[j];
        ulonglong2 zv = s_z[j];
        ulonglong2 wv = s_w[j];

        unsigned long long rA0, rB0, rA1, rB1;
        FMA2(rA0, ax, xv.x, wv.x);
        FMA2(rB0, ax, xv.y, wv.y);
        FMA2(rA1, bx, xv.x, wv.x);
        FMA2(rB1, bx, xv.y, wv.y);
        FMA2(rA0, ay, yv.x, rA0);
        FMA2(rB0, ay, yv.y, rB0);
        FMA2(rA1, by, yv.x, rA1);
        FMA2(rB1, by, yv.y, rB1);
        FMA2(rA0, az, zv.x, rA0);
        FMA2(rB0, az, zv.y, rB0);
        FMA2(rA1, bz, zv.x, rA1);
        FMA2(rB1, bz, zv.y, rB1);

        float r0, r1, r2, r3;
        UNPK2(r0, r1, rA0);
        UNPK2(r2, r3, rB0);
        float m = fminf(fminf(r0, r1), fminf(r2, r3));
        if (m < a2) {
            top3_insert(r0, a0, a1, a2);
            top3_insert(r1, a0, a1, a2);
            top3_insert(r2, a0, a1, a2);
            top3_insert(r3, a0, a1, a2);
        }
        float u0, u1, u2, u3;
        UNPK2(u0, u1, rA1);
        UNPK2(u2, u3, rB1);
        float mu = fminf(fminf(u0, u1), fminf(u2, u3));
        if (mu < c2) {
            top3_insert(u0, c0, c1, c2);
            top3_insert(u1, c0, c1, c2);
            top3_insert(u2, c0, c1, c2);
            top3_insert(u3, c0, c1, c2);
        }
    }

    int o0 = (sp * NQ + q0) * 3;
    g_part[o0 + 0] = a0;
    g_part[o0 + 1] = a1;
    g_part[o0 + 2] = a2;
    int o1 = (sp * NQ + q1) * 3;
    g_part[o1 + 0] = c0;
    g_part[o1 + 1] = c1;
    g_part[o1 + 2] = c2;
}

// ---------------- merge + coverage ----------------

__global__ __launch_bounds__(256) void merge_kernel() {
    int tid   = threadIdx.x;
    int chunk = blockIdx.x;
    int b     = chunk >> 6;
    int qbase = b * NPTS + (chunk & 63) * 256;
    int qid   = qbase + tid;

    float4 s  = g_q[qid];
    float  xq = -0.5f * s.x;
    bool   valid = (s.w >= 0.0f);
    float  sq = fmaxf(s.w, 0.0f);

    float b0 = 3e38f, b1 = 3e38f, b2 = 3e38f;
#pragma unroll
    for (int sp = 0; sp < SPLIT; sp++) {
        int o = (sp * NQ + qid) * 3;
        top3_insert(g_part[o + 0], b0, b1, b2);
        top3_insert(g_part[o + 1], b0, b1, b2);
        top3_insert(g_part[o + 2], b0, b1, b2);
    }

    float xc   = -0.5f * g_q[qbase + 128].x;
    int  winLo = window_lo(b, xc);

    float rq = sqrtf(fmaxf(b2 + sq, 0.0f));
    bool okL = (winLo == 0);
    if (!okL) {
        int bl = xbin(g_sx[b * NPTS + winLo]);
        okL = (xq - rq) >= (XMIN + (bl + 1) * WBIN);
    }
    bool okR = (winLo + WIN >= NPTS);
    if (!okR) {
        int br = xbin(g_sx[b * NPTS + winLo + WIN - 1]);
        okR = (xq + rq) <= (XMIN + br * WBIN);
    }

    if (valid && !(okL && okR)) {
        int fi = atomicAdd(&g_fbn, 1);
        g_fb[fi] = qid;
        g_d[qid] = 0.0f;   // overwritten by fallback
    } else {
        float dsum = sqrtf(fmaxf(b0 + sq, 0.0f))
                   + sqrtf(fmaxf(b1 + sq, 0.0f))
                   + sqrtf(fmaxf(b2 + sq, 0.0f));
        g_d[qid] = valid ? dsum : 0.0f;
    }
}

__global__ __launch_bounds__(256) void fallback_kernel() {
    __shared__ float fb3[256 * 3];
    int tid = threadIdx.x;
    int nfb = g_fbn;
    for (int fi = blockIdx.x; fi < nfb; fi += gridDim.x) {
        int qid = g_fb[fi];
        float4 ms = g_q[qid];
        float  msq = fmaxf(ms.w, 0.0f);
        int    mb  = qid >> 14;
        const float* bx = g_sx + mb * NPTS;
        const float* by = g_sy + mb * NPTS;
        const float* bz = g_sz + mb * NPTS;
        const float* bw = g_sw + mb * NPTS;

        float b0 = 3e38f, b1 = 3e38f, b2 = 3e38f;
        int beg = tid * (NPTS / 256);
        for (int k = 0; k < NPTS / 256; k++) {
            int i = beg + k;
            float r = fmaf(ms.x, bx[i], bw[i]);
            r = fmaf(ms.y, by[i], r);
            r = fmaf(ms.z, bz[i], r);
            top3_insert(r, b0, b1, b2);
        }
        fb3[tid * 3 + 0] = b0;
        fb3[tid * 3 + 1] = b1;
        fb3[tid * 3 + 2] = b2;
        __syncthreads();
        if (tid == 0) {
            float c0 = 3e38f, c1 = 3e38f, c2 = 3e38f;
            for (int i = 0; i < 256 * 3; i++)
                top3_insert(fb3[i], c0, c1, c2);
            g_d[qid] = sqrtf(fmaxf(c0 + msq, 0.0f))
                     + sqrtf(fmaxf(c1 + msq, 0.0f))
                     + sqrtf(fmaxf(c2 + msq, 0.0f));
        }
        __syncthreads();
    }
}

// ---------------- deterministic reduction ----------------

__global__ __launch_bounds__(256) void reduce_kernel() {
    __shared__ long long wsum[8];
    __shared__ int       wcnt[8];
    int tid  = threadIdx.x;
    int lane = tid & 31, warp = tid >> 5;
    int qid  = blockIdx.x * 256 + tid;

    bool valid = (g_q[qid].w >= 0.0f);
    float d = g_d[qid];
    long long v = __float2ll_rn(fminf(d, 1e5f) * 4294967296.0f);
#pragma unroll
    for (int o = 16; o; o >>= 1)
        v += __shfl_down_sync(0xffffffffu, v, o);
    int cnt = __popc(__ballot_sync(0xffffffffu, valid));
    if (lane == 0) { wsum[warp] = v; wcnt[warp] = cnt; }
    __syncthreads();
    if (tid == 0) {
        long long vs = 0; int cs = 0;
#pragma unroll
        for (int i = 0; i < 8; i++) { vs += wsum[i]; cs += wcnt[i]; }
        g_psum[blockIdx.x] = vs;
        g_pcnt[blockIdx.x] = cs;
    }
}

__global__ __launch_bounds__(256) void final_kernel(float* __restrict__ out) {
    __shared__ long long rs[NCHUNK];
    __shared__ int       rc[NCHUNK];
    int t = threadIdx.x;
    if (t < NCHUNK) { rs[t] = g_psum[t]; rc[t] = g_pcnt[t]; }
    __syncthreads();
    for (int o = 32; o; o >>= 1) {
        if (t < o) { rs[t] += rs[t + o]; rc[t] += rc[t + o]; }
        else if (t >= 64 && t < 64 + o) { rs[t] += rs[t + o]; rc[t] += rc[t + o]; }
        __syncthreads();
    }
    if (t == 0) {
        double S0 = (double)rs[0]  / 4294967296.0;
        double S1 = (double)rs[64] / 4294967296.0;
        float l0 = (float)(S0 / (3.0 * (double)max(rc[0],  1)));
        float l1 = (float)(S1 / (3.0 * (double)max(rc[64], 1)));
        out[0] = 0.5f * (l0 + l1);
        g_fbn = 0;                       // reset for next graph replay
    }
}

extern "C" void kernel_launch(void* const* d_in, const int* in_sizes, int n_in,
                              void* d_out, int out_size) {
    const float* src = (const float*)d_in[0];   // source_pc [2,64,2048,3]
    const float* tgt = (const float*)d_in[1];   // target_pc [2,3,64,2048]

    hist_kernel<<<NQ / 256, 256>>>(src, tgt);
    prefix_kernel<<<4, 256>>>();
    scatter_kernel<<<NQ / 256, 256>>>(src, tgt);
    dim3 gs(NCHUNK, SPLIT);
    scan_kernel<<<gs, KTHR>>>();
    merge_kernel<<<NCHUNK, 256>>>();
    fallback_kernel<<<64, 256>>>();
    reduce_kernel<<<NCHUNK, 256>>>();
    final_kernel<<<1, 256>>>((float*)d_out);
}

// round 15
// speedup vs baseline: 1.1522x; 1.1522x over previous
#include <cuda_runtime.h>

// knnLoss: x-counting-sort + fixed 2048-target window scan (exact w/ coverage
// check + radius-bounded per-query fallback). Separate graph-captured kernels.

#define NPTS   16384
#define NB     2
#define NQ     (NB * NPTS)
#define NBINS  512
#define XMIN   (-4.5f)
#define BINSCL (NBINS / 9.0f)
#define WBIN   (9.0f / NBINS)
#define WIN    2048
#define HWIN   (WIN / 2)
#define SPLIT  8
#define SEG    (WIN / SPLIT)      // 256 targets per scan block
#define KTHR   128                // scan block threads (QPT=2 -> 256 queries)
#define NCHUNK 128                // sorted 256-query chunks

__device__ int g_thist[NB * NBINS];
__device__ int g_qhist[NB * NBINS];
__device__ int g_tbase[NB * NBINS];
__device__ int g_tcur [NB * NBINS];
__device__ int g_qcur [NB * NBINS];
__device__ __align__(16) float g_sx[NQ];
__device__ __align__(16) float g_sy[NQ];
__device__ __align__(16) float g_sz[NQ];
__device__ __align__(16) float g_sw[NQ];
__device__ float4    g_q[NQ];
__device__ float     g_part[SPLIT * NQ * 3];
__device__ float     g_d[NQ];
__device__ float     g_rq[NQ];
__device__ int       g_fb[NQ];
__device__ int       g_fbn;          // zero-init; re-zeroed by final_kernel
__device__ long long g_psum[NCHUNK];
__device__ int       g_pcnt[NCHUNK];

#define FMA2(d, a, b, c) \
    asm("fma.rn.f32x2 %0, %1, %2, %3;" : "=l"(d) : "l"(a), "l"(b), "l"(c))
#define UNPK2(lo, hi, v) \
    asm("mov.b64 {%0, %1}, %2;" : "=f"(lo), "=f"(hi) : "l"(v))
#define DUP2(d, f) \
    asm("mov.b64 %0, {%1, %1};" : "=l"(d) : "f"(f))

__device__ __forceinline__ int xbin(float x) {
    int b = (int)((x - XMIN) * BINSCL);
    return min(max(b, 0), NBINS - 1);
}

__device__ __forceinline__ void top3_insert(float r, float& b0, float& b1, float& b2) {
    float m1 = fmaxf(r, b1);
    float m0 = fmaxf(r, b0);
    b2 = fminf(b2, m1);
    b1 = fminf(b1, m0);
    b0 = fminf(b0, r);
}

__device__ __forceinline__ int window_lo(int b, float xc) {
    int pos = g_tbase[b * NBINS + xbin(xc)];
    return (min(max(pos - HWIN, 0), NPTS - WIN)) & ~3;
}

// ---------------- pipeline ----------------

__global__ void hist_kernel(const float* __restrict__ src,
                            const float* __restrict__ tgt) {
    int i = blockIdx.x * blockDim.x + threadIdx.x;    // 0..NQ-1
    int b = i >> 14;
    int n = i & (NPTS - 1);
    int h = n >> 9;
    int w = n & 511;
    long sOff = (((long)b * 64 + 2 * h) * 2048 + 4 * w) * 3;
    long tOff = (long)b * 3 * 64 * 2048 + (long)(2 * h) * 2048 + 4 * w;
    atomicAdd(&g_thist[b * NBINS + xbin(tgt[tOff])], 1);
    atomicAdd(&g_qhist[b * NBINS + xbin(src[sOff])], 1);
}

__global__ __launch_bounds__(256) void prefix_kernel() {
    __shared__ int sh[NBINS];
    int t = threadIdx.x;
    int a = blockIdx.x;                               // 0..3
    const int* h = (a < 2) ? (g_thist + a * NBINS) : (g_qhist + (a - 2) * NBINS);
    int o0 = h[t];
    int o1 = h[t + 256];
    sh[t] = o0;
    sh[t + 256] = o1;
    __syncthreads();
    for (int off = 1; off < NBINS; off <<= 1) {
        int v0 = (t >= off) ? sh[t - off] : 0;
        int v1 = (t + 256 >= off) ? sh[t + 256 - off] : 0;
        __syncthreads();
        sh[t] += v0;
        sh[t + 256] += v1;
        __syncthreads();
    }
    int e0 = sh[t] - o0;
    int e1 = sh[t + 256] - o1;
    if (a < 2) {
        g_tbase[a * NBINS + t] = e0;
        g_tbase[a * NBINS + t + 256] = e1;
        g_tcur [a * NBINS + t] = e0;
        g_tcur [a * NBINS + t + 256] = e1;
    } else {
        g_qcur[(a - 2) * NBINS + t] = e0;
        g_qcur[(a - 2) * NBINS + t + 256] = e1;
    }
}

__global__ void scatter_kernel(const float* __restrict__ src,
                               const float* __restrict__ tgt) {
    int i = blockIdx.x * blockDim.x + threadIdx.x;
    // re-zero hists for the next graph replay (prefix already consumed them)
    if (i < NB * NBINS) g_thist[i] = 0;
    else if (i < 2 * NB * NBINS) g_qhist[i - NB * NBINS] = 0;

    int b = i >> 14;
    int n = i & (NPTS - 1);
    int h = n >> 9;
    int w = n & 511;
    long tOff = (long)b * 3 * 64 * 2048 + (long)(2 * h) * 2048 + 4 * w;
    float tx = tgt[tOff];
    float ty = tgt[tOff + 64 * 2048];
    float tz = tgt[tOff + 2L * 64 * 2048];
    bool  vt = (tx != 0.0f) || (ty != 0.0f) || (tz != 0.0f);
    float tw;
    if (vt) tw = tx * tx + ty * ty + tz * tz;
    else { tx = 0.0f; ty = 0.0f; tz = 0.0f; tw = 1e20f; }
    int tpos = atomicAdd(&g_tcur[b * NBINS + xbin(tx)], 1);
    int ts = b * NPTS + tpos;
    g_sx[ts] = tx; g_sy[ts] = ty; g_sz[ts] = tz; g_sw[ts] = tw;

    long sOff = (((long)b * 64 + 2 * h) * 2048 + 4 * w) * 3;
    float sx = src[sOff + 0];
    float sy = src[sOff + 1];
    float sz = src[sOff + 2];
    bool  vs = (sx != 0.0f) || (sy != 0.0f) || (sz != 0.0f);
    float sq = sx * sx + sy * sy + sz * sz;
    int qpos = atomicAdd(&g_qcur[b * NBINS + xbin(sx)], 1);
    g_q[b * NPTS + qpos] = make_float4(-2.0f * sx, -2.0f * sy, -2.0f * sz,
                                       vs ? sq : -1.0f);
}

// ---------------- hot kernel: balanced window scan ----------------

__global__ __launch_bounds__(KTHR) void scan_kernel() {
    __shared__ ulonglong2 s_x[SEG / 4], s_y[SEG / 4];
    __shared__ ulonglong2 s_z[SEG / 4], s_w[SEG / 4];

    int tid   = threadIdx.x;
    int chunk = blockIdx.x;                 // 0..127
    int sp    = blockIdx.y;                 // 0..SPLIT-1
    int b     = chunk >> 6;
    int qbase = b * NPTS + (chunk & 63) * 256;
    int q0    = qbase + tid;
    int q1    = q0 + KTHR;

    float4 sA = g_q[q0];
    float4 sB = g_q[q1];
    unsigned long long ax, ay, az, bx, by, bz;
    DUP2(ax, sA.x); DUP2(ay, sA.y); DUP2(az, sA.z);
    DUP2(bx, sB.x); DUP2(by, sB.y); DUP2(bz, sB.z);

    float xc = -0.5f * g_q[qbase + 128].x;
    int seg  = window_lo(b, xc) + sp * SEG;

    // cooperative tile load (SEG targets, SoA): 4*(SEG/4)=SEG quarter-tasks,
    // 128 threads -> 2 tasks each.
    {
        int gbase = b * NPTS + seg;
        if (tid < SEG / 4) {
            float4 vx = ((const float4*)(g_sx + gbase))[tid];
            float4 vz = ((const float4*)(g_sz + gbase))[tid];
            s_x[tid] = *(const ulonglong2*)&vx;
            s_z[tid] = *(const ulonglong2*)&vz;
        } else {
            int i2 = tid - SEG / 4;
            float4 vy = ((const float4*)(g_sy + gbase))[i2];
            float4 vw = ((const float4*)(g_sw + gbase))[i2];
            s_y[i2] = *(const ulonglong2*)&vy;
            s_w[i2] = *(const ulonglong2*)&vw;
        }
    }
    __syncthreads();

    float a0 = 3e38f, a1 = 3e38f, a2 = 3e38f;
    float c0 = 3e38f, c1 = 3e38f, c2 = 3e38f;

#pragma unroll 4
    for (int j = 0; j < SEG / 4; j++) {
        ulonglong2 xv = s_x[j];
        ulonglong2 yv = s_y[j];
        ulonglong2 zv = s_z[j];
        ulonglong2 wv = s_w[j];

        unsigned long long rA0, rB0, rA1, rB1;
        FMA2(rA0, ax, xv.x, wv.x);
        FMA2(rB0, ax, xv.y, wv.y);
        FMA2(rA1, bx, xv.x, wv.x);
        FMA2(rB1, bx, xv.y, wv.y);
        FMA2(rA0, ay, yv.x, rA0);
        FMA2(rB0, ay, yv.y, rB0);
        FMA2(rA1, by, yv.x, rA1);
        FMA2(rB1, by, yv.y, rB1);
        FMA2(rA0, az, zv.x, rA0);
        FMA2(rB0, az, zv.y, rB0);
        FMA2(rA1, bz, zv.x, rA1);
        FMA2(rB1, bz, zv.y, rB1);

        float r0, r1, r2, r3;
        UNPK2(r0, r1, rA0);
        UNPK2(r2, r3, rB0);
        float m = fminf(fminf(r0, r1), fminf(r2, r3));
        if (m < a2) {
            top3_insert(r0, a0, a1, a2);
            top3_insert(r1, a0, a1, a2);
            top3_insert(r2, a0, a1, a2);
            top3_insert(r3, a0, a1, a2);
        }
        float u0, u1, u2, u3;
        UNPK2(u0, u1, rA1);
        UNPK2(u2, u3, rB1);
        float mu = fminf(fminf(u0, u1), fminf(u2, u3));
        if (mu < c2) {
            top3_insert(u0, c0, c1, c2);
            top3_insert(u1, c0, c1, c2);
            top3_insert(u2, c0, c1, c2);
            top3_insert(u3, c0, c1, c2);
        }
    }

    int o0 = (sp * NQ + q0) * 3;
    g_part[o0 + 0] = a0;
    g_part[o0 + 1] = a1;
    g_part[o0 + 2] = a2;
    int o1 = (sp * NQ + q1) * 3;
    g_part[o1 + 0] = c0;
    g_part[o1 + 1] = c1;
    g_part[o1 + 2] = c2;
}

// ---------------- merge + coverage ----------------

__global__ __launch_bounds__(256) void merge_kernel() {
    int tid   = threadIdx.x;
    int chunk = blockIdx.x;
    int b     = chunk >> 6;
    int qbase = b * NPTS + (chunk & 63) * 256;
    int qid   = qbase + tid;

    float4 s  = g_q[qid];
    float  xq = -0.5f * s.x;
    bool   valid = (s.w >= 0.0f);
    float  sq = fmaxf(s.w, 0.0f);

    float b0 = 3e38f, b1 = 3e38f, b2 = 3e38f;
#pragma unroll
    for (int sp = 0; sp < SPLIT; sp++) {
        int o = (sp * NQ + qid) * 3;
        top3_insert(g_part[o + 0], b0, b1, b2);
        top3_insert(g_part[o + 1], b0, b1, b2);
        top3_insert(g_part[o + 2], b0, b1, b2);
    }

    float xc   = -0.5f * g_q[qbase + 128].x;
    int  winLo = window_lo(b, xc);

    float rq = sqrtf(fmaxf(b2 + sq, 0.0f));
    bool okL = (winLo == 0);
    if (!okL) {
        int bl = xbin(g_sx[b * NPTS + winLo]);
        okL = (xq - rq) >= (XMIN + (bl + 1) * WBIN);
    }
    bool okR = (winLo + WIN >= NPTS);
    if (!okR) {
        int br = xbin(g_sx[b * NPTS + winLo + WIN - 1]);
        okR = (xq + rq) <= (XMIN + br * WBIN);
    }

    if (valid && !(okL && okR)) {
        int fi = atomicAdd(&g_fbn, 1);
        g_fb[fi] = qid;
        g_rq[qid] = rq;
        g_d[qid] = 0.0f;   // overwritten by fallback
    } else {
        float dsum = sqrtf(fmaxf(b0 + sq, 0.0f))
                   + sqrtf(fmaxf(b1 + sq, 0.0f))
                   + sqrtf(fmaxf(b2 + sq, 0.0f));
        g_d[qid] = valid ? dsum : 0.0f;
    }
}

// radius-bounded exact rescan, thread-per-query.
// All true top-3 lie within |x - xq| <= rq (rq >= true d3), so the fresh top3
// over the bin range covering [xq-rq, xq+rq] is exact.
__global__ __launch_bounds__(256) void fallback_kernel() {
    int nfb = g_fbn;
    for (int fi = blockIdx.x * blockDim.x + threadIdx.x; fi < nfb;
         fi += gridDim.x * blockDim.x) {
        int qid = g_fb[fi];
        float4 ms = g_q[qid];
        float  xq = -0.5f * ms.x;
        float  msq = fmaxf(ms.w, 0.0f);
        float  rq  = g_rq[qid];
        int    mb  = qid >> 14;
        const float* bx = g_sx + mb * NPTS;
        const float* by = g_sy + mb * NPTS;
        const float* bz = g_sz + mb * NPTS;
        const float* bw = g_sw + mb * NPTS;

        int binL = xbin(xq - rq);
        int binR = xbin(xq + rq);
        int lo = g_tbase[mb * NBINS + binL];
        int hi = (binR >= NBINS - 1) ? NPTS : g_tbase[mb * NBINS + binR + 1];

        float b0 = 3e38f, b1 = 3e38f, b2 = 3e38f;
        for (int i = lo; i < hi; i++) {
            float r = fmaf(ms.x, bx[i], bw[i]);
            r = fmaf(ms.y, by[i], r);
            r = fmaf(ms.z, bz[i], r);
            if (r < b2) top3_insert(r, b0, b1, b2);
        }
        g_d[qid] = sqrtf(fmaxf(b0 + msq, 0.0f))
                 + sqrtf(fmaxf(b1 + msq, 0.0f))
                 + sqrtf(fmaxf(b2 + msq, 0.0f));
    }
}

// ---------------- deterministic reduction ----------------

__global__ __launch_bounds__(256) void reduce_kernel() {
    __shared__ long long wsum[8];
    __shared__ int       wcnt[8];
    int tid  = threadIdx.x;
    int lane = tid & 31, warp = tid >> 5;
    int qid  = blockIdx.x * 256 + tid;

    bool valid = (g_q[qid].w >= 0.0f);
    float d = g_d[qid];
    long long v = __float2ll_rn(fminf(d, 1e5f) * 4294967296.0f);
#pragma unroll
    for (int o = 16; o; o >>= 1)
        v += __shfl_down_sync(0xffffffffu, v, o);
    int cnt = __popc(__ballot_sync(0xffffffffu, valid));
    if (lane == 0) { wsum[warp] = v; wcnt[warp] = cnt; }
    __syncthreads();
    if (tid == 0) {
        long long vs = 0; int cs = 0;
#pragma unroll
        for (int i = 0; i < 8; i++) { vs += wsum[i]; cs += wcnt[i]; }
        g_psum[blockIdx.x] = vs;
        g_pcnt[blockIdx.x] = cs;
    }
}

__global__ __launch_bounds__(256) void final_kernel(float* __restrict__ out) {
    __shared__ long long rs[NCHUNK];
    __shared__ int       rc[NCHUNK];
    int t = threadIdx.x;
    if (t < NCHUNK) { rs[t] = g_psum[t]; rc[t] = g_pcnt[t]; }
    __syncthreads();
    for (int o = 32; o; o >>= 1) {
        if (t < o) { rs[t] += rs[t + o]; rc[t] += rc[t + o]; }
        else if (t >= 64 && t < 64 + o) { rs[t] += rs[t + o]; rc[t] += rc[t + o]; }
        __syncthreads();
    }
    if (t == 0) {
        double S0 = (double)rs[0]  / 4294967296.0;
        double S1 = (double)rs[64] / 4294967296.0;
        float l0 = (float)(S0 / (3.0 * (double)max(rc[0],  1)));
        float l1 = (float)(S1 / (3.0 * (double)max(rc[64], 1)));
        out[0] = 0.5f * (l0 + l1);
        g_fbn = 0;                       // reset for next graph replay
    }
}

extern "C" void kernel_launch(void* const* d_in, const int* in_sizes, int n_in,
                              void* d_out, int out_size) {
    const float* src = (const float*)d_in[0];   // source_pc [2,64,2048,3]
    const float* tgt = (const float*)d_in[1];   // target_pc [2,3,64,2048]

    hist_kernel<<<NQ / 256, 256>>>(src, tgt);
    prefix_kernel<<<4, 256>>>();
    scatter_kernel<<<NQ / 256, 256>>>(src, tgt);
    dim3 gs(NCHUNK, SPLIT);
    scan_kernel<<<gs, KTHR>>>();
    merge_kernel<<<NCHUNK, 256>>>();
    fallback_kernel<<<128, 256>>>();
    reduce_kernel<<<NCHUNK, 256>>>();
    final_kernel<<<1, 256>>>((float*)d_out);
}

// round 16
// speedup vs baseline: 8.2213x; 7.1356x over previous
#include <cuda_runtime.h>

// knnLoss: x-counting-sort + fixed 2048-target window scan + coverage check
// + WARP-COOPERATIVE radius-bounded exact fallback. Graph-captured kernels.

#define NPTS   16384
#define NB     2
#define NQ     (NB * NPTS)
#define NBINS  512
#define XMIN   (-4.5f)
#define BINSCL (NBINS / 9.0f)
#define WBIN   (9.0f / NBINS)
#define WIN    2048
#define HWIN   (WIN / 2)
#define SPLIT  8
#define SEG    (WIN / SPLIT)      // 256 targets per scan block
#define KTHR   128                // scan block threads (QPT=2 -> 256 queries)
#define NCHUNK 128                // sorted 256-query chunks

__device__ int g_thist[NB * NBINS];
__device__ int g_qhist[NB * NBINS];
__device__ int g_tbase[NB * NBINS];
__device__ int g_tcur [NB * NBINS];
__device__ int g_qcur [NB * NBINS];
__device__ __align__(16) float g_sx[NQ];
__device__ __align__(16) float g_sy[NQ];
__device__ __align__(16) float g_sz[NQ];
__device__ __align__(16) float g_sw[NQ];
__device__ float4    g_q[NQ];
__device__ float     g_part[SPLIT * NQ * 3];
__device__ float     g_d[NQ];
__device__ float     g_rq[NQ];
__device__ int       g_fb[NQ];
__device__ int       g_fbn;          // zero-init; re-zeroed by final_kernel
__device__ long long g_psum[NCHUNK];
__device__ int       g_pcnt[NCHUNK];

#define FMA2(d, a, b, c) \
    asm("fma.rn.f32x2 %0, %1, %2, %3;" : "=l"(d) : "l"(a), "l"(b), "l"(c))
#define UNPK2(lo, hi, v) \
    asm("mov.b64 {%0, %1}, %2;" : "=f"(lo), "=f"(hi) : "l"(v))
#define DUP2(d, f) \
    asm("mov.b64 %0, {%1, %1};" : "=l"(d) : "f"(f))

__device__ __forceinline__ int xbin(float x) {
    int b = (int)((x - XMIN) * BINSCL);
    return min(max(b, 0), NBINS - 1);
}

__device__ __forceinline__ void top3_insert(float r, float& b0, float& b1, float& b2) {
    float m1 = fmaxf(r, b1);
    float m0 = fmaxf(r, b0);
    b2 = fminf(b2, m1);
    b1 = fminf(b1, m0);
    b0 = fminf(b0, r);
}

__device__ __forceinline__ int window_lo(int b, float xc) {
    int pos = g_tbase[b * NBINS + xbin(xc)];
    return (min(max(pos - HWIN, 0), NPTS - WIN)) & ~3;
}

// ---------------- pipeline ----------------

__global__ void hist_kernel(const float* __restrict__ src,
                            const float* __restrict__ tgt) {
    int i = blockIdx.x * blockDim.x + threadIdx.x;    // 0..NQ-1
    int b = i >> 14;
    int n = i & (NPTS - 1);
    int h = n >> 9;
    int w = n & 511;
    long sOff = (((long)b * 64 + 2 * h) * 2048 + 4 * w) * 3;
    long tOff = (long)b * 3 * 64 * 2048 + (long)(2 * h) * 2048 + 4 * w;
    atomicAdd(&g_thist[b * NBINS + xbin(tgt[tOff])], 1);
    atomicAdd(&g_qhist[b * NBINS + xbin(src[sOff])], 1);
}

__global__ __launch_bounds__(256) void prefix_kernel() {
    __shared__ int sh[NBINS];
    int t = threadIdx.x;
    int a = blockIdx.x;                               // 0..3
    const int* h = (a < 2) ? (g_thist + a * NBINS) : (g_qhist + (a - 2) * NBINS);
    int o0 = h[t];
    int o1 = h[t + 256];
    sh[t] = o0;
    sh[t + 256] = o1;
    __syncthreads();
    for (int off = 1; off < NBINS; off <<= 1) {
        int v0 = (t >= off) ? sh[t - off] : 0;
        int v1 = (t + 256 >= off) ? sh[t + 256 - off] : 0;
        __syncthreads();
        sh[t] += v0;
        sh[t + 256] += v1;
        __syncthreads();
    }
    int e0 = sh[t] - o0;
    int e1 = sh[t + 256] - o1;
    if (a < 2) {
        g_tbase[a * NBINS + t] = e0;
        g_tbase[a * NBINS + t + 256] = e1;
        g_tcur [a * NBINS + t] = e0;
        g_tcur [a * NBINS + t + 256] = e1;
    } else {
        g_qcur[(a - 2) * NBINS + t] = e0;
        g_qcur[(a - 2) * NBINS + t + 256] = e1;
    }
}

__global__ void scatter_kernel(const float* __restrict__ src,
                               const float* __restrict__ tgt) {
    int i = blockIdx.x * blockDim.x + threadIdx.x;
    // re-zero hists for the next graph replay (prefix already consumed them)
    if (i < NB * NBINS) g_thist[i] = 0;
    else if (i < 2 * NB * NBINS) g_qhist[i - NB * NBINS] = 0;

    int b = i >> 14;
    int n = i & (NPTS - 1);
    int h = n >> 9;
    int w = n & 511;
    long tOff = (long)b * 3 * 64 * 2048 + (long)(2 * h) * 2048 + 4 * w;
    float tx = tgt[tOff];
    float ty = tgt[tOff + 64 * 2048];
    float tz = tgt[tOff + 2L * 64 * 2048];
    bool  vt = (tx != 0.0f) || (ty != 0.0f) || (tz != 0.0f);
    float tw;
    if (vt) tw = tx * tx + ty * ty + tz * tz;
    else { tx = 0.0f; ty = 0.0f; tz = 0.0f; tw = 1e20f; }
    int tpos = atomicAdd(&g_tcur[b * NBINS + xbin(tx)], 1);
    int ts = b * NPTS + tpos;
    g_sx[ts] = tx; g_sy[ts] = ty; g_sz[ts] = tz; g_sw[ts] = tw;

    long sOff = (((long)b * 64 + 2 * h) * 2048 + 4 * w) * 3;
    float sx = src[sOff + 0];
    float sy = src[sOff + 1];
    float sz = src[sOff + 2];
    bool  vs = (sx != 0.0f) || (sy != 0.0f) || (sz != 0.0f);
    float sq = sx * sx + sy * sy + sz * sz;
    int qpos = atomicAdd(&g_qcur[b * NBINS + xbin(sx)], 1);
    g_q[b * NPTS + qpos] = make_float4(-2.0f * sx, -2.0f * sy, -2.0f * sz,
                                       vs ? sq : -1.0f);
}

// ---------------- hot kernel: balanced window scan ----------------

__global__ __launch_bounds__(KTHR) void scan_kernel() {
    __shared__ ulonglong2 s_x[SEG / 4], s_y[SEG / 4];
    __shared__ ulonglong2 s_z[SEG / 4], s_w[SEG / 4];

    int tid   = threadIdx.x;
    int chunk = blockIdx.x;                 // 0..127
    int sp    = blockIdx.y;                 // 0..SPLIT-1
    int b     = chunk >> 6;
    int qbase = b * NPTS + (chunk & 63) * 256;
    int q0    = qbase + tid;
    int q1    = q0 + KTHR;

    float4 sA = g_q[q0];
    float4 sB = g_q[q1];
    unsigned long long ax, ay, az, bx, by, bz;
    DUP2(ax, sA.x); DUP2(ay, sA.y); DUP2(az, sA.z);
    DUP2(bx, sB.x); DUP2(by, sB.y); DUP2(bz, sB.z);

    float xc = -0.5f * g_q[qbase + 128].x;
    int seg  = window_lo(b, xc) + sp * SEG;

    {
        int gbase = b * NPTS + seg;
        if (tid < SEG / 4) {
            float4 vx = ((const float4*)(g_sx + gbase))[tid];
            float4 vz = ((const float4*)(g_sz + gbase))[tid];
            s_x[tid] = *(const ulonglong2*)&vx;
            s_z[tid] = *(const ulonglong2*)&vz;
        } else {
            int i2 = tid - SEG / 4;
            float4 vy = ((const float4*)(g_sy + gbase))[i2];
            float4 vw = ((const float4*)(g_sw + gbase))[i2];
            s_y[i2] = *(const ulonglong2*)&vy;
            s_w[i2] = *(const ulonglong2*)&vw;
        }
    }
    __syncthreads();

    float a0 = 3e38f, a1 = 3e38f, a2 = 3e38f;
    float c0 = 3e38f, c1 = 3e38f, c2 = 3e38f;

#pragma unroll 4
    for (int j = 0; j < SEG / 4; j++) {
        ulonglong2 xv = s_x[j];
        ulonglong2 yv = s_y[j];
        ulonglong2 zv = s_z[j];
        ulonglong2 wv = s_w[j];

        unsigned long long rA0, rB0, rA1, rB1;
        FMA2(rA0, ax, xv.x, wv.x);
        FMA2(rB0, ax, xv.y, wv.y);
        FMA2(rA1, bx, xv.x, wv.x);
        FMA2(rB1, bx, xv.y, wv.y);
        FMA2(rA0, ay, yv.x, rA0);
        FMA2(rB0, ay, yv.y, rB0);
        FMA2(rA1, by, yv.x, rA1);
        FMA2(rB1, by, yv.y, rB1);
        FMA2(rA0, az, zv.x, rA0);
        FMA2(rB0, az, zv.y, rB0);
        FMA2(rA1, bz, zv.x, rA1);
        FMA2(rB1, bz, zv.y, rB1);

        float r0, r1, r2, r3;
        UNPK2(r0, r1, rA0);
        UNPK2(r2, r3, rB0);
        float m = fminf(fminf(r0, r1), fminf(r2, r3));
        if (m < a2) {
            top3_insert(r0, a0, a1, a2);
            top3_insert(r1, a0, a1, a2);
            top3_insert(r2, a0, a1, a2);
            top3_insert(r3, a0, a1, a2);
        }
        float u0, u1, u2, u3;
        UNPK2(u0, u1, rA1);
        UNPK2(u2, u3, rB1);
        float mu = fminf(fminf(u0, u1), fminf(u2, u3));
        if (mu < c2) {
            top3_insert(u0, c0, c1, c2);
            top3_insert(u1, c0, c1, c2);
            top3_insert(u2, c0, c1, c2);
            top3_insert(u3, c0, c1, c2);
        }
    }

    int o0 = (sp * NQ + q0) * 3;
    g_part[o0 + 0] = a0;
    g_part[o0 + 1] = a1;
    g_part[o0 + 2] = a2;
    int o1 = (sp * NQ + q1) * 3;
    g_part[o1 + 0] = c0;
    g_part[o1 + 1] = c1;
    g_part[o1 + 2] = c2;
}

// ---------------- merge + coverage ----------------

__global__ __launch_bounds__(256) void merge_kernel() {
    int tid   = threadIdx.x;
    int chunk = blockIdx.x;
    int b     = chunk >> 6;
    int qbase = b * NPTS + (chunk & 63) * 256;
    int qid   = qbase + tid;

    float4 s  = g_q[qid];
    float  xq = -0.5f * s.x;
    bool   valid = (s.w >= 0.0f);
    float  sq = fmaxf(s.w, 0.0f);

    float b0 = 3e38f, b1 = 3e38f, b2 = 3e38f;
#pragma unroll
    for (int sp = 0; sp < SPLIT; sp++) {
        int o = (sp * NQ + qid) * 3;
        top3_insert(g_part[o + 0], b0, b1, b2);
        top3_insert(g_part[o + 1], b0, b1, b2);
        top3_insert(g_part[o + 2], b0, b1, b2);
    }

    float xc   = -0.5f * g_q[qbase + 128].x;
    int  winLo = window_lo(b, xc);

    float rq = sqrtf(fmaxf(b2 + sq, 0.0f));
    bool okL = (winLo == 0);
    if (!okL) {
        int bl = xbin(g_sx[b * NPTS + winLo]);
        okL = (xq - rq) >= (XMIN + (bl + 1) * WBIN);
    }
    bool okR = (winLo + WIN >= NPTS);
    if (!okR) {
        int br = xbin(g_sx[b * NPTS + winLo + WIN - 1]);
        okR = (xq + rq) <= (XMIN + br * WBIN);
    }

    if (valid && !(okL && okR)) {
        int fi = atomicAdd(&g_fbn, 1);
        g_fb[fi] = qid;
        g_rq[qid] = rq;
        g_d[qid] = 0.0f;   // overwritten by fallback
    } else {
        float dsum = sqrtf(fmaxf(b0 + sq, 0.0f))
                   + sqrtf(fmaxf(b1 + sq, 0.0f))
                   + sqrtf(fmaxf(b2 + sq, 0.0f));
        g_d[qid] = valid ? dsum : 0.0f;
    }
}

// WARP-COOPERATIVE radius-bounded exact rescan: one warp per failed query,
// lanes stride the bin-index range (coalesced SoA loads), per-lane top3,
// shfl-merged (order-invariant => exact & deterministic).
__global__ __launch_bounds__(256) void fallback_kernel() {
    int nfb   = g_fbn;
    int lane  = threadIdx.x & 31;
    int gwarp = (blockIdx.x * blockDim.x + threadIdx.x) >> 5;
    int nwarp = (gridDim.x * blockDim.x) >> 5;

    for (int fi = gwarp; fi < nfb; fi += nwarp) {
        int qid = g_fb[fi];
        float4 ms = g_q[qid];
        float  xq = -0.5f * ms.x;
        float  msq = fmaxf(ms.w, 0.0f);
        float  rq  = g_rq[qid];
        int    mb  = qid >> 14;
        const float* bx = g_sx + mb * NPTS;
        const float* by = g_sy + mb * NPTS;
        const float* bz = g_sz + mb * NPTS;
        const float* bw = g_sw + mb * NPTS;

        int binL = xbin(xq - rq);
        int binR = xbin(xq + rq);
        int lo = g_tbase[mb * NBINS + binL];
        int hi = (binR >= NBINS - 1) ? NPTS : g_tbase[mb * NBINS + binR + 1];

        float b0 = 3e38f, b1 = 3e38f, b2 = 3e38f;
        for (int i = lo + lane; i < hi; i += 32) {
            float r = fmaf(ms.x, __ldg(bx + i), __ldg(bw + i));
            r = fmaf(ms.y, __ldg(by + i), r);
            r = fmaf(ms.z, __ldg(bz + i), r);
            if (r < b2) top3_insert(r, b0, b1, b2);
        }
#pragma unroll
        for (int o = 16; o; o >>= 1) {
            float t0 = __shfl_down_sync(0xffffffffu, b0, o);
            float t1 = __shfl_down_sync(0xffffffffu, b1, o);
            float t2 = __shfl_down_sync(0xffffffffu, b2, o);
            top3_insert(t0, b0, b1, b2);
            top3_insert(t1, b0, b1, b2);
            top3_insert(t2, b0, b1, b2);
        }
        if (lane == 0) {
            g_d[qid] = sqrtf(fmaxf(b0 + msq, 0.0f))
                     + sqrtf(fmaxf(b1 + msq, 0.0f))
                     + sqrtf(fmaxf(b2 + msq, 0.0f));
        }
    }
}

// ---------------- deterministic reduction ----------------

__global__ __launch_bounds__(256) void reduce_kernel() {
    __shared__ long long wsum[8];
    __shared__ int       wcnt[8];
    int tid  = threadIdx.x;
    int lane = tid & 31, warp = tid >> 5;
    int qid  = blockIdx.x * 256 + tid;

    bool valid = (g_q[qid].w >= 0.0f);
    float d = g_d[qid];
    long long v = __float2ll_rn(fminf(d, 1e5f) * 4294967296.0f);
#pragma unroll
    for (int o = 16; o; o >>= 1)
        v += __shfl_down_sync(0xffffffffu, v, o);
    int cnt = __popc(__ballot_sync(0xffffffffu, valid));
    if (lane == 0) { wsum[warp] = v; wcnt[warp] = cnt; }
    __syncthreads();
    if (tid == 0) {
        long long vs = 0; int cs = 0;
#pragma unroll
        for (int i = 0; i < 8; i++) { vs += wsum[i]; cs += wcnt[i]; }
        g_psum[blockIdx.x] = vs;
        g_pcnt[blockIdx.x] = cs;
    }
}

__global__ __launch_bounds__(256) void final_kernel(float* __restrict__ out) {
    __shared__ long long rs[NCHUNK];
    __shared__ int       rc[NCHUNK];
    int t = threadIdx.x;
    if (t < NCHUNK) { rs[t] = g_psum[t]; rc[t] = g_pcnt[t]; }
    __syncthreads();
    for (int o = 32; o; o >>= 1) {
        if (t < o) { rs[t] += rs[t + o]; rc[t] += rc[t + o]; }
        else if (t >= 64 && t < 64 + o) { rs[t] += rs[t + o]; rc[t] += rc[t + o]; }
        __syncthreads();
    }
    if (t == 0) {
        double S0 = (double)rs[0]  / 4294967296.0;
        double S1 = (double)rs[64] / 4294967296.0;
        float l0 = (float)(S0 / (3.0 * (double)max(rc[0],  1)));
        float l1 = (float)(S1 / (3.0 * (double)max(rc[64], 1)));
        out[0] = 0.5f * (l0 + l1);
        g_fbn = 0;                       // reset for next graph replay
    }
}

extern "C" void kernel_launch(void* const* d_in, const int* in_sizes, int n_in,
                              void* d_out, int out_size) {
    const float* src = (const float*)d_in[0];   // source_pc [2,64,2048,3]
    const float* tgt = (const float*)d_in[1];   // target_pc [2,3,64,2048]

    hist_kernel<<<NQ / 256, 256>>>(src, tgt);
    prefix_kernel<<<4, 256>>>();
    scatter_kernel<<<NQ / 256, 256>>>(src, tgt);
    dim3 gs(NCHUNK, SPLIT);
    scan_kernel<<<gs, KTHR>>>();
    merge_kernel<<<NCHUNK, 256>>>();
    fallback_kernel<<<256, 256>>>();
    reduce_kernel<<<NCHUNK, 256>>>();
    final_kernel<<<1, 256>>>((float*)d_out);
}